// round 4
// baseline (speedup 1.0000x reference)
#include <cuda_runtime.h>

#define HPF 32
#define NBLK 20
#define HID 640
#define BATCHN 128
#define SEQ 512
#define INSZ 16
#define TPB 64
#define NCTA 1280          // 20 j-blocks * 64 batch-pairs

// ---- packed fp32x2 helpers (sm_103a dual fp32) ----
__device__ __forceinline__ unsigned long long pk2(float a, float b) {
    unsigned long long r;
    asm("mov.b64 %0, {%1, %2};" : "=l"(r) : "f"(a), "f"(b));
    return r;
}
__device__ __forceinline__ float2 upk2(unsigned long long v) {
    float2 f;
    asm("mov.b64 {%0, %1}, %2;" : "=f"(f.x), "=f"(f.y) : "l"(v));
    return f;
}
__device__ __forceinline__ void fma2(unsigned long long& d,
                                     unsigned long long a, unsigned long long b) {
    asm("fma.rn.f32x2 %0, %1, %2, %0;" : "+l"(d) : "l"(a), "l"(b));
}

__device__ __forceinline__ float sigm(float x) {
    return __fdividef(1.0f, 1.0f + __expf(-x));
}
__device__ __forceinline__ float tanhfast(float x) {
    return 2.0f * __fdividef(1.0f, 1.0f + __expf(-2.0f * x)) - 1.0f;
}

__global__ __launch_bounds__(TPB, 9)
void lstm_fused_kernel(const float* __restrict__ x,
                       const float* __restrict__ Ui, const float* __restrict__ Vi, const float* __restrict__ bi,
                       const float* __restrict__ Uf, const float* __restrict__ Vf, const float* __restrict__ bf,
                       const float* __restrict__ Uc, const float* __restrict__ Vc, const float* __restrict__ bc,
                       const float* __restrict__ Uo, const float* __restrict__ Vo, const float* __restrict__ bo,
                       float* __restrict__ out, long long out_size)
{
    // h stage: [batch 0..1][32 cols], 16B aligned for LDS.128
    __shared__ __align__(16) float hs[2 * HPF];
    // partial-gate exchange: [writer warp][local gate][lane]
    __shared__ __align__(16) unsigned long long xch[2][2][HPF];

    const int w    = threadIdx.x >> 5;        // 0: gates i,f   1: gates c,o
    const int lane = threadIdx.x & 31;
    const int j    = blockIdx.x % NBLK;       // hidden block 0..19
    const int grp  = blockIdx.x / NBLK;       // 0..63
    const int b0   = grp * 2;
    const int bmy  = b0 + w;                  // batch this warp epilogues
    const int col  = j * HPF + lane;

    const float* Vg[4] = {Vi, Vf, Vc, Vo};
    const float* Ug[4] = {Ui, Uf, Uc, Uo};
    const float* Bg[4] = {bi, bf, bc, bo};

    // ---- this warp's 2 gate V-blocks -> registers, packed over m-pairs ----
    // vr[l][q] = ( V_{2w+l}[2q][n], V_{2w+l}[2q+1][n] ),  n = lane
    unsigned long long vr[2][16];
    #pragma unroll
    for (int l = 0; l < 2; ++l) {
        const float* V = Vg[2 * w + l];
        #pragma unroll
        for (int q = 0; q < 16; ++q) {
            const float v0 = __ldg(&V[(j * HPF + 2 * q)     * HID + col]);
            const float v1 = __ldg(&V[(j * HPF + 2 * q + 1) * HID + col]);
            vr[l][q] = pk2(v0, v1);
        }
    }

    // ---- all-gate bias + folded input projection (used only in epilogue) ----
    float ua[4], ub[4], bias[4];
    #pragma unroll
    for (int g = 0; g < 4; ++g) {
        float a = 0.0f, bb = 0.0f;
        if (j < 16) a = __ldg(&Ug[g][j * HID + col]);
        if (j == 0) { a += __ldg(&Ug[g][16 * HID + col]); bb = __ldg(&Ug[g][17 * HID + col]); }
        if (j == 2) { a += __ldg(&Ug[g][18 * HID + col]); bb = __ldg(&Ug[g][19 * HID + col]); }
        ua[g] = a; ub[g] = bb;
        bias[g] = __ldg(&Bg[g][col]);
    }
    const int fa = (j == 0) ? 0 : ((j == 2) ? 2 : ((j < 16) ? j : 0));
    const int fb = (j == 0) ? 1 : ((j == 2) ? 3 : 0);   // ub==0 when unused

    const float* xq = x + (long long)bmy * SEQ * INSZ;
    float* outp = out + (long long)bmy * SEQ * HID + col;

    float h = 0.0f, c = 0.0f;
    hs[w * HPF + lane] = 0.0f;
    __syncthreads();

    for (int t = 0; t < SEQ; ++t) {
        // prefetch x for this warp's epilogue batch (latency hidden by matvec)
        const float xa = __ldg(xq + t * INSZ + fa);
        const float xb = __ldg(xq + t * INSZ + fb);

        // acc[k][l]: batch k, local gate l; lo = even-m partial, hi = odd-m
        unsigned long long acc[2][2];
        acc[0][0] = 0ull; acc[0][1] = 0ull; acc[1][0] = 0ull; acc[1][1] = 0ull;

        #pragma unroll
        for (int q = 0; q < 8; ++q) {
            // h[k][4q..4q+3] as two packed f32x2
            const ulonglong2 h0 = *reinterpret_cast<const ulonglong2*>(hs + 4 * q);
            const ulonglong2 h1 = *reinterpret_cast<const ulonglong2*>(hs + HPF + 4 * q);
            fma2(acc[0][0], h0.x, vr[0][2 * q]);
            fma2(acc[0][1], h0.x, vr[1][2 * q]);
            fma2(acc[1][0], h1.x, vr[0][2 * q]);
            fma2(acc[1][1], h1.x, vr[1][2 * q]);
            fma2(acc[0][0], h0.y, vr[0][2 * q + 1]);
            fma2(acc[0][1], h0.y, vr[1][2 * q + 1]);
            fma2(acc[1][0], h1.y, vr[0][2 * q + 1]);
            fma2(acc[1][1], h1.y, vr[1][2 * q + 1]);
        }

        // send partials for the batch the peer epilogues
        xch[w][0][lane] = acc[1 - w][0];
        xch[w][1][lane] = acc[1 - w][1];
        __syncthreads();   // also: all h reads above complete before h rewrite below

        // gates for my batch: own 2 (gates 2w,2w+1) + peer 2 (gates 2(1-w),2(1-w)+1)
        float gate[4];
        #pragma unroll
        for (int l = 0; l < 2; ++l) {
            const float2 po = upk2(acc[w][l]);
            gate[2 * w + l] = po.x + po.y;
            const float2 pp = upk2(xch[1 - w][l][lane]);
            gate[2 * (1 - w) + l] = pp.x + pp.y;
        }
        #pragma unroll
        for (int g = 0; g < 4; ++g)
            gate[g] += fmaf(xb, ub[g], fmaf(xa, ua[g], bias[g]));

        const float it = sigm(gate[0]);
        const float ft = sigm(gate[1]);
        const float gt = tanhfast(gate[2]);
        const float ot = sigm(gate[3]);

        c = ft * c + it * gt;
        h = ot * tanhfast(c);

        outp[(long long)t * HID] = h;
        hs[w * HPF + lane] = h;
        __syncthreads();   // h(t) visible to both warps before next matvec
    }

    // final (h_t, c_t) appended after hidden_seq when present in output buffer
    const long long hsz = (long long)BATCHN * SEQ * HID;
    if (out_size >= hsz + 2LL * BATCHN * HID) {
        out[hsz + (long long)bmy * HID + col] = h;
        out[hsz + (long long)BATCHN * HID + (long long)bmy * HID + col] = c;
    }
}

extern "C" void kernel_launch(void* const* d_in, const int* in_sizes, int n_in,
                              void* d_out, int out_size)
{
    const float* x  = (const float*)d_in[0];
    const float* Ui = (const float*)d_in[1];
    const float* Vi = (const float*)d_in[2];
    const float* bi = (const float*)d_in[3];
    const float* Uf = (const float*)d_in[4];
    const float* Vf = (const float*)d_in[5];
    const float* bf = (const float*)d_in[6];
    const float* Uc = (const float*)d_in[7];
    const float* Vc = (const float*)d_in[8];
    const float* bc = (const float*)d_in[9];
    const float* Uo = (const float*)d_in[10];
    const float* Vo = (const float*)d_in[11];
    const float* bo = (const float*)d_in[12];
    float* out = (float*)d_out;

    lstm_fused_kernel<<<NCTA, TPB>>>(
        x, Ui, Vi, bi, Uf, Vf, bf, Uc, Vc, bc, Uo, Vo, bo,
        out, (long long)out_size);
}

// round 5
// speedup vs baseline: 1.2125x; 1.2125x over previous
#include <cuda_runtime.h>

#define HPF 32
#define NBLK 20
#define HID 640
#define BATCHN 128
#define SEQ 512
#define INSZ 16
#define NCTA 1280          // 20 j-blocks * 64 batch-pairs (1 warp per CTA, NB=2)

// ---- packed fp32x2 helpers (sm_103a dual fp32) ----
__device__ __forceinline__ unsigned long long pk2(float a, float b) {
    unsigned long long r;
    asm("mov.b64 %0, {%1, %2};" : "=l"(r) : "f"(a), "f"(b));
    return r;
}
__device__ __forceinline__ float2 upk2(unsigned long long v) {
    float2 f;
    asm("mov.b64 {%0, %1}, %2;" : "=f"(f.x), "=f"(f.y) : "l"(v));
    return f;
}
__device__ __forceinline__ void fma2(unsigned long long& d,
                                     unsigned long long a, unsigned long long b) {
    asm("fma.rn.f32x2 %0, %1, %2, %0;" : "+l"(d) : "l"(a), "l"(b));
}
__device__ __forceinline__ float tanhapx(float x) {
    float r;
    asm("tanh.approx.f32 %0, %1;" : "=f"(r) : "f"(x));
    return r;
}

__global__ __launch_bounds__(32, 9)
void lstm_fused_kernel(const float* __restrict__ x,
                       const float* __restrict__ Ui, const float* __restrict__ Vi, const float* __restrict__ bi,
                       const float* __restrict__ Uf, const float* __restrict__ Vf, const float* __restrict__ bf,
                       const float* __restrict__ Uc, const float* __restrict__ Vc, const float* __restrict__ bc,
                       const float* __restrict__ Uo, const float* __restrict__ Vo, const float* __restrict__ bo,
                       float* __restrict__ out, long long out_size)
{
    // warp-private h stage, double buffered: [buf][batch][col]
    __shared__ __align__(16) float hs[2][2][HPF];

    const int lane = threadIdx.x;
    const int j    = blockIdx.x % NBLK;       // hidden block 0..19
    const int grp  = blockIdx.x / NBLK;       // 0..63
    const int b0   = grp * 2;
    const int col  = j * HPF + lane;

    const float* Vg[4] = {Vi, Vf, Vc, Vo};
    const float* Ug[4] = {Ui, Uf, Uc, Uo};
    const float* Bg[4] = {bi, bf, bc, bo};

    // ---- all 4 gate V-blocks -> registers, packed over m-pairs ----
    // vr[g][q] = ( V_g[2q][col], V_g[2q+1][col] )
    unsigned long long vr[4][16];
    #pragma unroll
    for (int g = 0; g < 4; ++g) {
        #pragma unroll
        for (int q = 0; q < 16; ++q) {
            const float v0 = __ldg(&Vg[g][(j * HPF + 2 * q)     * HID + col]);
            const float v1 = __ldg(&Vg[g][(j * HPF + 2 * q + 1) * HID + col]);
            vr[g][q] = pk2(v0, v1);
        }
    }

    // ---- bias + folded masked-U input projection ----
    float ua[4], ub[4], bias[4];
    #pragma unroll
    for (int g = 0; g < 4; ++g) {
        float a = 0.0f, bb = 0.0f;
        if (j < 16) a = __ldg(&Ug[g][j * HID + col]);
        if (j == 0) { a += __ldg(&Ug[g][16 * HID + col]); bb = __ldg(&Ug[g][17 * HID + col]); }
        if (j == 2) { a += __ldg(&Ug[g][18 * HID + col]); bb = __ldg(&Ug[g][19 * HID + col]); }
        ua[g] = a; ub[g] = bb;
        bias[g] = __ldg(&Bg[g][col]);
    }
    const int fa = (j == 0) ? 0 : ((j == 2) ? 2 : ((j < 16) ? j : 0));
    const int fb = (j == 0) ? 1 : ((j == 2) ? 3 : 0);   // ub==0 when unused

    const float* xq0 = x + (long long)(b0 + 0) * SEQ * INSZ;
    const float* xq1 = x + (long long)(b0 + 1) * SEQ * INSZ;
    float* outp0 = out + (long long)(b0 + 0) * SEQ * HID + col;
    float* outp1 = out + (long long)(b0 + 1) * SEQ * HID + col;

    float h0 = 0.0f, c0 = 0.0f, h1 = 0.0f, c1 = 0.0f;
    hs[0][0][lane] = 0.0f; hs[0][1][lane] = 0.0f;
    hs[1][0][lane] = 0.0f; hs[1][1][lane] = 0.0f;
    __syncwarp();

    for (int t = 0; t < SEQ; ++t) {
        const float* rb = &hs[t & 1][0][0];          // holds h(t-1)
        float*       wb = &hs[(t + 1) & 1][0][0];    // will hold h(t)

        const float xa0 = __ldg(xq0 + t * INSZ + fa);
        const float xb0 = __ldg(xq0 + t * INSZ + fb);
        const float xa1 = __ldg(xq1 + t * INSZ + fa);
        const float xb1 = __ldg(xq1 + t * INSZ + fb);

        unsigned long long acc[2][4];
        #pragma unroll
        for (int g = 0; g < 4; ++g) { acc[0][g] = 0ull; acc[1][g] = 0ull; }

        #pragma unroll
        for (int q = 0; q < 8; ++q) {
            const ulonglong2 ha = *reinterpret_cast<const ulonglong2*>(rb + 4 * q);
            const ulonglong2 hb = *reinterpret_cast<const ulonglong2*>(rb + HPF + 4 * q);
            #pragma unroll
            for (int g = 0; g < 4; ++g) {
                fma2(acc[0][g], ha.x, vr[g][2 * q]);
                fma2(acc[1][g], hb.x, vr[g][2 * q]);
                fma2(acc[0][g], ha.y, vr[g][2 * q + 1]);
                fma2(acc[1][g], hb.y, vr[g][2 * q + 1]);
            }
        }
        __syncwarp();   // h reads done before wb overwrite isn't needed (different buffer),
                        // but keeps the stage coherent across iterations cheaply.

        // ---- epilogue batch 0 ----
        {
            const float2 pi = upk2(acc[0][0]);
            const float2 pf = upk2(acc[0][1]);
            const float2 pc = upk2(acc[0][2]);
            const float2 po = upk2(acc[0][3]);
            const float gi = pi.x + pi.y + fmaf(xa0, ua[0], fmaf(xb0, ub[0], bias[0]));
            const float gf = pf.x + pf.y + fmaf(xa0, ua[1], fmaf(xb0, ub[1], bias[1]));
            const float gg = pc.x + pc.y + fmaf(xa0, ua[2], fmaf(xb0, ub[2], bias[2]));
            const float go = po.x + po.y + fmaf(xa0, ua[3], fmaf(xb0, ub[3], bias[3]));
            const float ti = tanhapx(0.5f * gi);
            const float tf = tanhapx(0.5f * gf);
            const float tg = tanhapx(gg);
            const float to = tanhapx(0.5f * go);
            const float it = fmaf(0.5f, ti, 0.5f);
            const float ft = fmaf(0.5f, tf, 0.5f);
            const float ot = fmaf(0.5f, to, 0.5f);
            c0 = fmaf(ft, c0, it * tg);
            h0 = ot * tanhapx(c0);
            outp0[(long long)t * HID] = h0;
            wb[lane] = h0;
        }
        // ---- epilogue batch 1 ----
        {
            const float2 pi = upk2(acc[1][0]);
            const float2 pf = upk2(acc[1][1]);
            const float2 pc = upk2(acc[1][2]);
            const float2 po = upk2(acc[1][3]);
            const float gi = pi.x + pi.y + fmaf(xa1, ua[0], fmaf(xb1, ub[0], bias[0]));
            const float gf = pf.x + pf.y + fmaf(xa1, ua[1], fmaf(xb1, ub[1], bias[1]));
            const float gg = pc.x + pc.y + fmaf(xa1, ua[2], fmaf(xb1, ub[2], bias[2]));
            const float go = po.x + po.y + fmaf(xa1, ua[3], fmaf(xb1, ub[3], bias[3]));
            const float ti = tanhapx(0.5f * gi);
            const float tf = tanhapx(0.5f * gf);
            const float tg = tanhapx(gg);
            const float to = tanhapx(0.5f * go);
            const float it = fmaf(0.5f, ti, 0.5f);
            const float ft = fmaf(0.5f, tf, 0.5f);
            const float ot = fmaf(0.5f, to, 0.5f);
            c1 = fmaf(ft, c1, it * tg);
            h1 = ot * tanhapx(c1);
            outp1[(long long)t * HID] = h1;
            wb[HPF + lane] = h1;
        }
        __syncwarp();   // h(t) visible before next step's reads
    }

    // final (h_t, c_t) appended after hidden_seq when present in output buffer
    const long long hsz = (long long)BATCHN * SEQ * HID;
    if (out_size >= hsz + 2LL * BATCHN * HID) {
        out[hsz + (long long)(b0 + 0) * HID + col] = h0;
        out[hsz + (long long)(b0 + 1) * HID + col] = h1;
        out[hsz + (long long)BATCHN * HID + (long long)(b0 + 0) * HID + col] = c0;
        out[hsz + (long long)BATCHN * HID + (long long)(b0 + 1) * HID + col] = c1;
    }
}

extern "C" void kernel_launch(void* const* d_in, const int* in_sizes, int n_in,
                              void* d_out, int out_size)
{
    const float* x  = (const float*)d_in[0];
    const float* Ui = (const float*)d_in[1];
    const float* Vi = (const float*)d_in[2];
    const float* bi = (const float*)d_in[3];
    const float* Uf = (const float*)d_in[4];
    const float* Vf = (const float*)d_in[5];
    const float* bf = (const float*)d_in[6];
    const float* Uc = (const float*)d_in[7];
    const float* Vc = (const float*)d_in[8];
    const float* bc = (const float*)d_in[9];
    const float* Uo = (const float*)d_in[10];
    const float* Vo = (const float*)d_in[11];
    const float* bo = (const float*)d_in[12];
    float* out = (float*)d_out;

    lstm_fused_kernel<<<NCTA, 32>>>(
        x, Ui, Vi, bi, Uf, Vf, bf, Uc, Vc, bc, Uo, Vo, bo,
        out, (long long)out_size);
}